// round 1
// baseline (speedup 1.0000x reference)
#include <cuda_runtime.h>
#include <math.h>

namespace {
constexpr int B = 2, T = 2048, C = 2048, H = 16, KVH = 4, D = 128;
constexpr int M = B * T;      // 4096
constexpr int HD = H * D;     // 2048
constexpr int KVD = KVH * D;  // 512
constexpr float EPS = 1e-6f;
constexpr float SCALE = 0.08838834764831845f;  // 1/sqrt(128)
}

// Scratch (allocation-guard-safe __device__ globals)
__device__ float g_q[(size_t)B * H * T * D];      // [B,H,T,D]
__device__ float g_k[(size_t)B * KVH * T * D];    // [B,KVH,T,D]
__device__ float g_v[(size_t)B * KVH * T * D];    // [B,KVH,T,D]
__device__ float g_att[(size_t)B * T * H * D];    // [B,T,H*D]

// ---------------------------------------------------------------------------
// GEMM: out = A[Mm,Kk] * W[Nn,Kk]^T + bias
// mode 0: out row-major [Mm,Nn]
// mode 1: out[(b*heads + h)*T + t][d]  with row=b*T+t, col=h*D+d (D=128=BN tile)
// ---------------------------------------------------------------------------
__global__ __launch_bounds__(256) void gemm_nt(
    const float* __restrict__ A, const float* __restrict__ W,
    const float* __restrict__ bias, float* __restrict__ out,
    int Mm, int Nn, int Kk, int mode, int heads)
{
  __shared__ float As[16][132];
  __shared__ float Bs[16][132];
  const int tid = threadIdx.x;
  const int bm = blockIdx.y * 128, bn = blockIdx.x * 128;
  const int ty = tid >> 4, tx = tid & 15;

  float acc[8][8];
#pragma unroll
  for (int i = 0; i < 8; i++)
#pragma unroll
    for (int j = 0; j < 8; j++) acc[i][j] = 0.0f;

  for (int k0 = 0; k0 < Kk; k0 += 16) {
#pragma unroll
    for (int q = 0; q < 2; q++) {
      int idx = tid + q * 256;
      int m = idx >> 2;
      int k4 = (idx & 3) << 2;
      float4 av = *(const float4*)(A + (size_t)(bm + m) * Kk + k0 + k4);
      As[k4 + 0][m] = av.x;
      As[k4 + 1][m] = av.y;
      As[k4 + 2][m] = av.z;
      As[k4 + 3][m] = av.w;
      float4 wv = *(const float4*)(W + (size_t)(bn + m) * Kk + k0 + k4);
      Bs[k4 + 0][m] = wv.x;
      Bs[k4 + 1][m] = wv.y;
      Bs[k4 + 2][m] = wv.z;
      Bs[k4 + 3][m] = wv.w;
    }
    __syncthreads();
#pragma unroll
    for (int kk = 0; kk < 16; kk++) {
      float4 a0 = *(const float4*)&As[kk][ty << 3];
      float4 a1 = *(const float4*)&As[kk][(ty << 3) + 4];
      float4 b0 = *(const float4*)&Bs[kk][tx << 3];
      float4 b1 = *(const float4*)&Bs[kk][(tx << 3) + 4];
      float af[8] = {a0.x, a0.y, a0.z, a0.w, a1.x, a1.y, a1.z, a1.w};
      float bf[8] = {b0.x, b0.y, b0.z, b0.w, b1.x, b1.y, b1.z, b1.w};
#pragma unroll
      for (int i = 0; i < 8; i++)
#pragma unroll
        for (int j = 0; j < 8; j++) acc[i][j] = fmaf(af[i], bf[j], acc[i][j]);
    }
    __syncthreads();
  }

#pragma unroll
  for (int i = 0; i < 8; i++) {
    int row = bm + (ty << 3) + i;
    int bb = row / T;
    int t = row - bb * T;
#pragma unroll
    for (int j = 0; j < 8; j++) {
      int col = bn + (tx << 3) + j;
      float v = acc[i][j] + (bias ? bias[col] : 0.0f);
      if (mode == 0) {
        out[(size_t)row * Nn + col] = v;
      } else {
        int hh = col >> 7;
        int d = col & 127;
        out[(((size_t)bb * heads + hh) * T + t) * D + d] = v;
      }
    }
  }
}

// ---------------------------------------------------------------------------
// Fused per-head RMSNorm + RoPE, in place. One warp per (b,h,t) row of D=128.
// lane holds d = lane + 32*j, so rotate_half is lane-local.
// ---------------------------------------------------------------------------
__global__ __launch_bounds__(256) void normrope_kernel(
    float* __restrict__ data, const float* __restrict__ w,
    const float* __restrict__ cg, const float* __restrict__ sg, int nrows)
{
  int gw = (blockIdx.x * 256 + threadIdx.x) >> 5;
  int lane = threadIdx.x & 31;
  if (gw >= nrows) return;
  int t = gw % T;
  float* row = data + (size_t)gw * D;

  float v[4];
#pragma unroll
  for (int j = 0; j < 4; j++) v[j] = row[lane + 32 * j];
  float ss = v[0] * v[0] + v[1] * v[1] + v[2] * v[2] + v[3] * v[3];
#pragma unroll
  for (int off = 16; off >= 1; off >>= 1)
    ss += __shfl_xor_sync(0xffffffffu, ss, off);
  float rinv = rsqrtf(ss * (1.0f / D) + EPS);
  float n[4];
#pragma unroll
  for (int j = 0; j < 4; j++) n[j] = w[lane + 32 * j] * v[j] * rinv;
  float rot[4] = {-n[2], -n[3], n[0], n[1]};
#pragma unroll
  for (int j = 0; j < 4; j++) {
    int d = lane + 32 * j;
    row[d] = fmaf(n[j], cg[t * D + d], rot[j] * sg[t * D + d]);
  }
}

// ---------------------------------------------------------------------------
// Causal flash attention, fp32. BQ=BK=64, 256 threads, one block per
// (q-tile, h, b). Q/K tiles stored transposed in smem (stride 68: float4
// aligned + conflict-free), V row-major, P through smem.
// ---------------------------------------------------------------------------
namespace {
constexpr int FA_SQT = 128 * 68;
constexpr int FA_SKT = 128 * 68;
constexpr int FA_SV = 64 * 128;
constexpr int FA_SP = 64 * 66;
constexpr size_t FA_SMEM_BYTES = (size_t)(FA_SQT + FA_SKT + FA_SV + FA_SP) * sizeof(float);
}

__global__ __launch_bounds__(256) void flash_kernel(
    const float* __restrict__ qg, const float* __restrict__ kg,
    const float* __restrict__ vg, float* __restrict__ att)
{
  extern __shared__ float sm[];
  float* sQT = sm;
  float* sKT = sQT + FA_SQT;
  float* sV = sKT + FA_SKT;
  float* sP = sV + FA_SV;

  const int tid = threadIdx.x;
  const int qblk = blockIdx.x;
  const int h = blockIdx.y;
  const int b = blockIdx.z;
  const int kvh = h / (H / KVH);
  const int t0 = qblk * 64;
  const int ty = tid >> 4, tx = tid & 15;

  const float* qbase = qg + (((size_t)b * H + h) * T + t0) * D;
  const float* kbase0 = kg + (((size_t)b * KVH + kvh) * T) * D;
  const float* vbase0 = vg + (((size_t)b * KVH + kvh) * T) * D;

  // Load Q tile (once), transposed: sQT[d][r]
  for (int i = tid; i < 64 * 32; i += 256) {
    int r = i & 63, d4 = i >> 6;
    float4 qv = *(const float4*)(qbase + (size_t)r * D + (d4 << 2));
    sQT[(d4 * 4 + 0) * 68 + r] = qv.x;
    sQT[(d4 * 4 + 1) * 68 + r] = qv.y;
    sQT[(d4 * 4 + 2) * 68 + r] = qv.z;
    sQT[(d4 * 4 + 3) * 68 + r] = qv.w;
  }

  float acc[4][8];
#pragma unroll
  for (int i = 0; i < 4; i++)
#pragma unroll
    for (int j = 0; j < 8; j++) acc[i][j] = 0.0f;
  float mrun[4] = {-1e30f, -1e30f, -1e30f, -1e30f};
  float lrun[4] = {0.f, 0.f, 0.f, 0.f};

  for (int kt = 0; kt <= qblk; kt++) {
    const int kc0 = kt * 64;
    __syncthreads();  // prior iter's reads of sKT/sV/sP done; Q visible on iter 0

    const float* kb = kbase0 + (size_t)kc0 * D;
    for (int i = tid; i < 64 * 32; i += 256) {
      int c = i & 63, d4 = i >> 6;
      float4 kv4 = *(const float4*)(kb + (size_t)c * D + (d4 << 2));
      sKT[(d4 * 4 + 0) * 68 + c] = kv4.x;
      sKT[(d4 * 4 + 1) * 68 + c] = kv4.y;
      sKT[(d4 * 4 + 2) * 68 + c] = kv4.z;
      sKT[(d4 * 4 + 3) * 68 + c] = kv4.w;
    }
    const float* vb = vbase0 + (size_t)kc0 * D;
    for (int i = tid; i < 64 * 32; i += 256) {
      int c = i >> 5, d4 = i & 31;
      *(float4*)&sV[c * 128 + (d4 << 2)] =
          *(const float4*)(vb + (size_t)c * D + (d4 << 2));
    }
    __syncthreads();

    // S = Q K^T fragment (4 rows x 4 cols per thread)
    float s[4][4];
#pragma unroll
    for (int i = 0; i < 4; i++)
#pragma unroll
      for (int j = 0; j < 4; j++) s[i][j] = 0.0f;

#pragma unroll 4
    for (int kk = 0; kk < 128; kk++) {
      float4 qf = *(const float4*)&sQT[kk * 68 + (ty << 2)];
      float4 kf = *(const float4*)&sKT[kk * 68 + (tx << 2)];
      float qa[4] = {qf.x, qf.y, qf.z, qf.w};
      float ka[4] = {kf.x, kf.y, kf.z, kf.w};
#pragma unroll
      for (int i = 0; i < 4; i++)
#pragma unroll
        for (int j = 0; j < 4; j++) s[i][j] = fmaf(qa[i], ka[j], s[i][j]);
    }

    const bool diag = (kt == qblk);
#pragma unroll
    for (int i = 0; i < 4; i++) {
      int grow = t0 + (ty << 2) + i;
#pragma unroll
      for (int j = 0; j < 4; j++) {
        float sv = s[i][j] * SCALE;
        if (diag && (kc0 + (tx << 2) + j > grow)) sv = -1e30f;
        s[i][j] = sv;
      }
    }

    // Online softmax: reductions over the 16 tx lanes owning each row.
#pragma unroll
    for (int i = 0; i < 4; i++) {
      float mx = fmaxf(fmaxf(s[i][0], s[i][1]), fmaxf(s[i][2], s[i][3]));
#pragma unroll
      for (int off = 8; off >= 1; off >>= 1)
        mx = fmaxf(mx, __shfl_xor_sync(0xffffffffu, mx, off));
      float mnew = fmaxf(mrun[i], mx);
      float fac = __expf(mrun[i] - mnew);
      mrun[i] = mnew;
      float rs = 0.f;
#pragma unroll
      for (int j = 0; j < 4; j++) {
        float p = __expf(s[i][j] - mnew);
        sP[((ty << 2) + i) * 66 + (tx << 2) + j] = p;
        rs += p;
      }
#pragma unroll
      for (int off = 8; off >= 1; off >>= 1)
        rs += __shfl_xor_sync(0xffffffffu, rs, off);
      lrun[i] = lrun[i] * fac + rs;
#pragma unroll
      for (int j = 0; j < 8; j++) acc[i][j] *= fac;
    }
    __syncthreads();

    // O += P * V  (thread: 4 rows x 8 d-cols)
#pragma unroll 2
    for (int c = 0; c < 64; c++) {
      float4 v0 = *(const float4*)&sV[c * 128 + (tx << 3)];
      float4 v1 = *(const float4*)&sV[c * 128 + (tx << 3) + 4];
      float va[8] = {v0.x, v0.y, v0.z, v0.w, v1.x, v1.y, v1.z, v1.w};
#pragma unroll
      for (int i = 0; i < 4; i++) {
        float p = sP[((ty << 2) + i) * 66 + c];
#pragma unroll
        for (int j = 0; j < 8; j++) acc[i][j] = fmaf(p, va[j], acc[i][j]);
      }
    }
  }

  // Epilogue: normalize and store to [B,T,H*D]
#pragma unroll
  for (int i = 0; i < 4; i++) {
    float inv = 1.0f / lrun[i];
    int t = t0 + (ty << 2) + i;
    float* op = att + (((size_t)b * T + t) * H + h) * D + (tx << 3);
    float4 o0 = make_float4(acc[i][0] * inv, acc[i][1] * inv, acc[i][2] * inv,
                            acc[i][3] * inv);
    float4 o1 = make_float4(acc[i][4] * inv, acc[i][5] * inv, acc[i][6] * inv,
                            acc[i][7] * inv);
    *(float4*)op = o0;
    *(float4*)(op + 4) = o1;
  }
}

// ---------------------------------------------------------------------------
extern "C" void kernel_launch(void* const* d_in, const int* in_sizes, int n_in,
                              void* d_out, int out_size) {
  (void)in_sizes; (void)n_in; (void)out_size;
  const float* x  = (const float*)d_in[0];
  const float* cg = (const float*)d_in[1];
  const float* sg = (const float*)d_in[2];
  const float* Wq = (const float*)d_in[3];
  const float* bq = (const float*)d_in[4];
  const float* Wk = (const float*)d_in[5];
  const float* bk = (const float*)d_in[6];
  const float* Wv = (const float*)d_in[7];
  const float* bv = (const float*)d_in[8];
  const float* Wo = (const float*)d_in[9];
  const float* qn = (const float*)d_in[10];
  const float* kn = (const float*)d_in[11];
  float* out = (float*)d_out;

  float *pq, *pk, *pv, *patt;
  cudaGetSymbolAddress((void**)&pq, g_q);
  cudaGetSymbolAddress((void**)&pk, g_k);
  cudaGetSymbolAddress((void**)&pv, g_v);
  cudaGetSymbolAddress((void**)&patt, g_att);

  cudaFuncSetAttribute(flash_kernel, cudaFuncAttributeMaxDynamicSharedMemorySize,
                       (int)FA_SMEM_BYTES);

  dim3 thr(256);
  // QKV projections (epilogue writes head-transposed layouts)
  gemm_nt<<<dim3(HD / 128, M / 128), thr>>>(x, Wq, bq, pq, M, HD, C, 1, H);
  gemm_nt<<<dim3(KVD / 128, M / 128), thr>>>(x, Wk, bk, pk, M, KVD, C, 1, KVH);
  gemm_nt<<<dim3(KVD / 128, M / 128), thr>>>(x, Wv, bv, pv, M, KVD, C, 1, KVH);
  // Per-head RMSNorm + RoPE (in place) on q and k
  normrope_kernel<<<(B * H * T) / 8, thr>>>(pq, qn, cg, sg, B * H * T);
  normrope_kernel<<<(B * KVH * T) / 8, thr>>>(pk, kn, cg, sg, B * KVH * T);
  // Causal GQA flash attention -> [B,T,H*D]
  flash_kernel<<<dim3(T / 64, H, B), thr, FA_SMEM_BYTES>>>(pq, pk, pv, patt);
  // Output projection
  gemm_nt<<<dim3(C / 128, M / 128), thr>>>(patt, Wo, nullptr, out, M, C, HD, 0, 0);
}

// round 5
// speedup vs baseline: 1.6964x; 1.6964x over previous
#include <cuda_runtime.h>
#include <cstdint>
#include <math.h>

namespace {
constexpr int B = 2, T = 2048, C = 2048, H = 16, KVH = 4, D = 128;
constexpr int M = B * T;      // 4096
constexpr int HD = H * D;     // 2048
constexpr int KVD = KVH * D;  // 512
constexpr float EPS = 1e-6f;
constexpr float SCALE = 0.08838834764831845f;  // 1/sqrt(128)
}

// Scratch (allocation-guard-safe __device__ globals)
__device__ float g_q[(size_t)B * H * T * D];      // [B,H,T,D]
__device__ float g_k[(size_t)B * KVH * T * D];    // [B,KVH,T,D]
__device__ float g_v[(size_t)B * KVH * T * D];    // [B,KVH,T,D]
__device__ float g_att[(size_t)B * T * H * D];    // [B,T,H*D]

__device__ __forceinline__ uint32_t f32_to_tf32(float v) {
  uint32_t o;
  asm("cvt.rna.tf32.f32 %0, %1;" : "=r"(o) : "f"(v));
  return o;
}

__device__ __forceinline__ void mma_tf32(float* c, const uint32_t* a,
                                         const uint32_t* b) {
  asm volatile(
      "mma.sync.aligned.m16n8k8.row.col.f32.tf32.tf32.f32 "
      "{%0,%1,%2,%3}, {%4,%5,%6,%7}, {%8,%9}, {%0,%1,%2,%3};"
      : "+f"(c[0]), "+f"(c[1]), "+f"(c[2]), "+f"(c[3])
      : "r"(a[0]), "r"(a[1]), "r"(a[2]), "r"(a[3]), "r"(b[0]), "r"(b[1]));
}

// ---------------------------------------------------------------------------
// HMMA tf32 GEMM: out = A[Mm,Kk] * W[Nn,Kk]^T + bias
// CTA 128x128, 8 warps (2M x 4N), warp tile 64x32, K-chunk 16, double buffer.
// mode 0: out row-major [Mm,Nn]
// mode 1: out[(b*heads+h)*T + t][d], row=b*T+t, col=h*128+d
// ---------------------------------------------------------------------------
__global__ __launch_bounds__(256) void gemm_mma(
    const float* __restrict__ A, const float* __restrict__ W,
    const float* __restrict__ bias, float* __restrict__ out,
    int Nn, int Kk, int mode, int heads)
{
  __shared__ uint32_t sA[2][128][20];
  __shared__ uint32_t sB[2][128][20];

  const int tid = threadIdx.x;
  const int lane = tid & 31;
  const int wid = tid >> 5;
  const int warp_m = wid & 1;        // 0..1
  const int warp_n = wid >> 1;       // 0..3
  const int gid = lane >> 2;         // groupID 0..7
  const int tig = lane & 3;          // thread-in-group 0..3
  const int bm = blockIdx.y * 128, bn = blockIdx.x * 128;

  // Global load mapping: 2 float4 per thread per matrix per chunk.
  const int lr = tid >> 2;
  const int lc = (tid & 3) << 2;
  const float* gA = A + (size_t)(bm + lr) * Kk + lc;
  const float* gA2 = A + (size_t)(bm + lr + 64) * Kk + lc;
  const float* gW = W + (size_t)(bn + lr) * Kk + lc;
  const float* gW2 = W + (size_t)(bn + lr + 64) * Kk + lc;

  float acc[4][4][4];
#pragma unroll
  for (int i = 0; i < 4; i++)
#pragma unroll
    for (int j = 0; j < 4; j++)
#pragma unroll
      for (int r = 0; r < 4; r++) acc[i][j][r] = 0.0f;

  const int NKC = Kk >> 4;

  float4 pa0, pa1, pw0, pw1;
  // preload chunk 0
  pa0 = *(const float4*)(gA);
  pa1 = *(const float4*)(gA2);
  pw0 = *(const float4*)(gW);
  pw1 = *(const float4*)(gW2);

  for (int kc = 0; kc < NKC; kc++) {
    const int buf = kc & 1;
    // STS current prefetched chunk (convert fp32 -> tf32 bits)
    {
      uint32_t* pA = &sA[buf][lr][lc];
      pA[0] = f32_to_tf32(pa0.x); pA[1] = f32_to_tf32(pa0.y);
      pA[2] = f32_to_tf32(pa0.z); pA[3] = f32_to_tf32(pa0.w);
      uint32_t* pA2 = &sA[buf][lr + 64][lc];
      pA2[0] = f32_to_tf32(pa1.x); pA2[1] = f32_to_tf32(pa1.y);
      pA2[2] = f32_to_tf32(pa1.z); pA2[3] = f32_to_tf32(pa1.w);
      uint32_t* pB = &sB[buf][lr][lc];
      pB[0] = f32_to_tf32(pw0.x); pB[1] = f32_to_tf32(pw0.y);
      pB[2] = f32_to_tf32(pw0.z); pB[3] = f32_to_tf32(pw0.w);
      uint32_t* pB2 = &sB[buf][lr + 64][lc];
      pB2[0] = f32_to_tf32(pw1.x); pB2[1] = f32_to_tf32(pw1.y);
      pB2[2] = f32_to_tf32(pw1.z); pB2[3] = f32_to_tf32(pw1.w);
    }
    __syncthreads();

    // Issue gmem loads for next chunk (overlap with compute)
    if (kc + 1 < NKC) {
      const int off = (kc + 1) << 4;
      pa0 = *(const float4*)(gA + off);
      pa1 = *(const float4*)(gA2 + off);
      pw0 = *(const float4*)(gW + off);
      pw1 = *(const float4*)(gW2 + off);
    }

    // Compute: 2 k8-steps over this chunk
#pragma unroll
    for (int k8 = 0; k8 < 2; k8++) {
      const int kcol = (k8 << 3) + tig;
      uint32_t bfrag[4][2];
#pragma unroll
      for (int nt = 0; nt < 4; nt++) {
        const int n = warp_n * 32 + nt * 8 + gid;
        bfrag[nt][0] = sB[buf][n][kcol];
        bfrag[nt][1] = sB[buf][n][kcol + 4];
      }
#pragma unroll
      for (int mt = 0; mt < 4; mt++) {
        const int m = warp_m * 64 + mt * 16 + gid;
        uint32_t afrag[4];
        afrag[0] = sA[buf][m][kcol];
        afrag[1] = sA[buf][m + 8][kcol];
        afrag[2] = sA[buf][m][kcol + 4];
        afrag[3] = sA[buf][m + 8][kcol + 4];
#pragma unroll
        for (int nt = 0; nt < 4; nt++)
          mma_tf32(acc[mt][nt], afrag, bfrag[nt]);
      }
    }
    __syncthreads();
  }

  // Epilogue
#pragma unroll
  for (int mt = 0; mt < 4; mt++) {
    const int row0 = bm + warp_m * 64 + mt * 16 + gid;
#pragma unroll
    for (int nt = 0; nt < 4; nt++) {
      const int col0 = bn + warp_n * 32 + nt * 8 + 2 * tig;
      const float b0 = bias ? bias[col0] : 0.0f;
      const float b1 = bias ? bias[col0 + 1] : 0.0f;
#pragma unroll
      for (int half = 0; half < 2; half++) {
        const int row = row0 + half * 8;
        float2 v;
        v.x = acc[mt][nt][half * 2 + 0] + b0;
        v.y = acc[mt][nt][half * 2 + 1] + b1;
        if (mode == 0) {
          *(float2*)(out + (size_t)row * Nn + col0) = v;
        } else {
          const int bb = row >> 11;       // row / T
          const int t = row & (T - 1);    // row % T
          const int hh = col0 >> 7;
          const int d = col0 & 127;
          *(float2*)(out + (((size_t)bb * heads + hh) * T + t) * D + d) = v;
        }
      }
    }
  }
}

// ---------------------------------------------------------------------------
// Fused per-head RMSNorm + RoPE, in place. One warp per (b,h,t) row of D=128.
// ---------------------------------------------------------------------------
__global__ __launch_bounds__(256) void normrope_kernel(
    float* __restrict__ data, const float* __restrict__ w,
    const float* __restrict__ cg, const float* __restrict__ sg, int nrows)
{
  int gw = (blockIdx.x * 256 + threadIdx.x) >> 5;
  int lane = threadIdx.x & 31;
  if (gw >= nrows) return;
  int t = gw % T;
  float* row = data + (size_t)gw * D;

  float v[4];
#pragma unroll
  for (int j = 0; j < 4; j++) v[j] = row[lane + 32 * j];
  float ss = v[0] * v[0] + v[1] * v[1] + v[2] * v[2] + v[3] * v[3];
#pragma unroll
  for (int off = 16; off >= 1; off >>= 1)
    ss += __shfl_xor_sync(0xffffffffu, ss, off);
  float rinv = rsqrtf(ss * (1.0f / D) + EPS);
  float n[4];
#pragma unroll
  for (int j = 0; j < 4; j++) n[j] = w[lane + 32 * j] * v[j] * rinv;
  float rot[4] = {-n[2], -n[3], n[0], n[1]};
#pragma unroll
  for (int j = 0; j < 4; j++) {
    int d = lane + 32 * j;
    row[d] = fmaf(n[j], cg[t * D + d], rot[j] * sg[t * D + d]);
  }
}

// ---------------------------------------------------------------------------
// Causal flash attention, fp32 (unchanged).
// ---------------------------------------------------------------------------
namespace {
constexpr int FA_SQT = 128 * 68;
constexpr int FA_SKT = 128 * 68;
constexpr int FA_SV = 64 * 128;
constexpr int FA_SP = 64 * 66;
constexpr size_t FA_SMEM_BYTES = (size_t)(FA_SQT + FA_SKT + FA_SV + FA_SP) * sizeof(float);
}

__global__ __launch_bounds__(256) void flash_kernel(
    const float* __restrict__ qg, const float* __restrict__ kg,
    const float* __restrict__ vg, float* __restrict__ att)
{
  extern __shared__ float sm[];
  float* sQT = sm;
  float* sKT = sQT + FA_SQT;
  float* sV = sKT + FA_SKT;
  float* sP = sV + FA_SV;

  const int tid = threadIdx.x;
  const int qblk = blockIdx.x;
  const int h = blockIdx.y;
  const int b = blockIdx.z;
  const int kvh = h / (H / KVH);
  const int t0 = qblk * 64;
  const int ty = tid >> 4, tx = tid & 15;

  const float* qbase = qg + (((size_t)b * H + h) * T + t0) * D;
  const float* kbase0 = kg + (((size_t)b * KVH + kvh) * T) * D;
  const float* vbase0 = vg + (((size_t)b * KVH + kvh) * T) * D;

  for (int i = tid; i < 64 * 32; i += 256) {
    int r = i & 63, d4 = i >> 6;
    float4 qv = *(const float4*)(qbase + (size_t)r * D + (d4 << 2));
    sQT[(d4 * 4 + 0) * 68 + r] = qv.x;
    sQT[(d4 * 4 + 1) * 68 + r] = qv.y;
    sQT[(d4 * 4 + 2) * 68 + r] = qv.z;
    sQT[(d4 * 4 + 3) * 68 + r] = qv.w;
  }

  float acc[4][8];
#pragma unroll
  for (int i = 0; i < 4; i++)
#pragma unroll
    for (int j = 0; j < 8; j++) acc[i][j] = 0.0f;
  float mrun[4] = {-1e30f, -1e30f, -1e30f, -1e30f};
  float lrun[4] = {0.f, 0.f, 0.f, 0.f};

  for (int kt = 0; kt <= qblk; kt++) {
    const int kc0 = kt * 64;
    __syncthreads();

    const float* kb = kbase0 + (size_t)kc0 * D;
    for (int i = tid; i < 64 * 32; i += 256) {
      int c = i & 63, d4 = i >> 6;
      float4 kv4 = *(const float4*)(kb + (size_t)c * D + (d4 << 2));
      sKT[(d4 * 4 + 0) * 68 + c] = kv4.x;
      sKT[(d4 * 4 + 1) * 68 + c] = kv4.y;
      sKT[(d4 * 4 + 2) * 68 + c] = kv4.z;
      sKT[(d4 * 4 + 3) * 68 + c] = kv4.w;
    }
    const float* vb = vbase0 + (size_t)kc0 * D;
    for (int i = tid; i < 64 * 32; i += 256) {
      int c = i >> 5, d4 = i & 31;
      *(float4*)&sV[c * 128 + (d4 << 2)] =
          *(const float4*)(vb + (size_t)c * D + (d4 << 2));
    }
    __syncthreads();

    float s[4][4];
#pragma unroll
    for (int i = 0; i < 4; i++)
#pragma unroll
      for (int j = 0; j < 4; j++) s[i][j] = 0.0f;

#pragma unroll 4
    for (int kk = 0; kk < 128; kk++) {
      float4 qf = *(const float4*)&sQT[kk * 68 + (ty << 2)];
      float4 kf = *(const float4*)&sKT[kk * 68 + (tx << 2)];
      float qa[4] = {qf.x, qf.y, qf.z, qf.w};
      float ka[4] = {kf.x, kf.y, kf.z, kf.w};
#pragma unroll
      for (int i = 0; i < 4; i++)
#pragma unroll
        for (int j = 0; j < 4; j++) s[i][j] = fmaf(qa[i], ka[j], s[i][j]);
    }

    const bool diag = (kt == qblk);
#pragma unroll
    for (int i = 0; i < 4; i++) {
      int grow = t0 + (ty << 2) + i;
#pragma unroll
      for (int j = 0; j < 4; j++) {
        float sv = s[i][j] * SCALE;
        if (diag && (kc0 + (tx << 2) + j > grow)) sv = -1e30f;
        s[i][j] = sv;
      }
    }

#pragma unroll
    for (int i = 0; i < 4; i++) {
      float mx = fmaxf(fmaxf(s[i][0], s[i][1]), fmaxf(s[i][2], s[i][3]));
#pragma unroll
      for (int off = 8; off >= 1; off >>= 1)
        mx = fmaxf(mx, __shfl_xor_sync(0xffffffffu, mx, off));
      float mnew = fmaxf(mrun[i], mx);
      float fac = __expf(mrun[i] - mnew);
      mrun[i] = mnew;
      float rs = 0.f;
#pragma unroll
      for (int j = 0; j < 4; j++) {
        float p = __expf(s[i][j] - mnew);
        sP[((ty << 2) + i) * 66 + (tx << 2) + j] = p;
        rs += p;
      }
#pragma unroll
      for (int off = 8; off >= 1; off >>= 1)
        rs += __shfl_xor_sync(0xffffffffu, rs, off);
      lrun[i] = lrun[i] * fac + rs;
#pragma unroll
      for (int j = 0; j < 8; j++) acc[i][j] *= fac;
    }
    __syncthreads();

#pragma unroll 2
    for (int c = 0; c < 64; c++) {
      float4 v0 = *(const float4*)&sV[c * 128 + (tx << 3)];
      float4 v1 = *(const float4*)&sV[c * 128 + (tx << 3) + 4];
      float va[8] = {v0.x, v0.y, v0.z, v0.w, v1.x, v1.y, v1.z, v1.w};
#pragma unroll
      for (int i = 0; i < 4; i++) {
        float p = sP[((ty << 2) + i) * 66 + c];
#pragma unroll
        for (int j = 0; j < 8; j++) acc[i][j] = fmaf(p, va[j], acc[i][j]);
      }
    }
  }

#pragma unroll
  for (int i = 0; i < 4; i++) {
    float inv = 1.0f / lrun[i];
    int t = t0 + (ty << 2) + i;
    float* op = att + (((size_t)b * T + t) * H + h) * D + (tx << 3);
    float4 o0 = make_float4(acc[i][0] * inv, acc[i][1] * inv, acc[i][2] * inv,
                            acc[i][3] * inv);
    float4 o1 = make_float4(acc[i][4] * inv, acc[i][5] * inv, acc[i][6] * inv,
                            acc[i][7] * inv);
    *(float4*)op = o0;
    *(float4*)(op + 4) = o1;
  }
}

// ---------------------------------------------------------------------------
extern "C" void kernel_launch(void* const* d_in, const int* in_sizes, int n_in,
                              void* d_out, int out_size) {
  (void)in_sizes; (void)n_in; (void)out_size;
  const float* x  = (const float*)d_in[0];
  const float* cg = (const float*)d_in[1];
  const float* sg = (const float*)d_in[2];
  const float* Wq = (const float*)d_in[3];
  const float* bq = (const float*)d_in[4];
  const float* Wk = (const float*)d_in[5];
  const float* bk = (const float*)d_in[6];
  const float* Wv = (const float*)d_in[7];
  const float* bv = (const float*)d_in[8];
  const float* Wo = (const float*)d_in[9];
  const float* qn = (const float*)d_in[10];
  const float* kn = (const float*)d_in[11];
  float* out = (float*)d_out;

  float *pq, *pk, *pv, *patt;
  cudaGetSymbolAddress((void**)&pq, g_q);
  cudaGetSymbolAddress((void**)&pk, g_k);
  cudaGetSymbolAddress((void**)&pv, g_v);
  cudaGetSymbolAddress((void**)&patt, g_att);

  cudaFuncSetAttribute(flash_kernel, cudaFuncAttributeMaxDynamicSharedMemorySize,
                       (int)FA_SMEM_BYTES);

  dim3 thr(256);
  // QKV projections on HMMA tf32 (epilogue writes head-transposed layouts)
  gemm_mma<<<dim3(HD / 128, M / 128), thr>>>(x, Wq, bq, pq, HD, C, 1, H);
  gemm_mma<<<dim3(KVD / 128, M / 128), thr>>>(x, Wk, bk, pk, KVD, C, 1, KVH);
  gemm_mma<<<dim3(KVD / 128, M / 128), thr>>>(x, Wv, bv, pv, KVD, C, 1, KVH);
  // Per-head RMSNorm + RoPE (in place) on q and k
  normrope_kernel<<<(B * H * T) / 8, thr>>>(pq, qn, cg, sg, B * H * T);
  normrope_kernel<<<(B * KVH * T) / 8, thr>>>(pk, kn, cg, sg, B * KVH * T);
  // Causal GQA flash attention -> [B,T,H*D]
  flash_kernel<<<dim3(T / 64, H, B), thr, FA_SMEM_BYTES>>>(pq, pk, pv, patt);
  // Output projection on HMMA tf32
  gemm_mma<<<dim3(C / 128, M / 128), thr>>>(patt, Wo, nullptr, out, C, HD, 0, 0);
}